// round 1
// baseline (speedup 1.0000x reference)
#include <cuda_runtime.h>

// Problem constants (fixed shapes per reference)
#define BATCH 16
#define IC1   128
#define OCN   256
#define ZDIM  64
#define HIN   64
#define WIN   64
#define HO    32
#define WO    32
#define NPIX  (HO*WO)          // 1024
#define NGRP  8
#define CPG   (OCN/NGRP)       // 32
#define EPSV  1e-5f

#define NW1  (OCN*IC1*9)       // 294912
#define NW2  (OCN*OCN*9)       // 589824
#define NWSC (OCN*IC1)         // 32768

// Scratch (static device globals; no allocation allowed)
__device__ float g_w1 [(size_t)BATCH*NW1];
__device__ float g_w2 [(size_t)BATCH*NW2];
__device__ float g_wsc[(size_t)BATCH*NWSC];
__device__ float g_act1 [(size_t)BATCH*OCN*NPIX];
__device__ float g_conv2[(size_t)BATCH*OCN*NPIX];
__device__ float g_sc   [(size_t)BATCH*OCN*NPIX];
__device__ float g_stats1[BATCH*NGRP*2];
__device__ float g_stats2[BATCH*NGRP*2];

// ---------------------------------------------------------------------------
// Weight modulation: out[b, i] = base[i] + head_b[i] + dot(z[b,:], head_w[i,:])
// Each thread owns one weight row i, reads head_w row ONCE (64 floats), and
// produces results for all 16 batches (z lives in smem).
// ---------------------------------------------------------------------------
__global__ __launch_bounds__(256) void modw_kernel(
    const float* __restrict__ base, const float* __restrict__ hw,
    const float* __restrict__ hb,   const float* __restrict__ z,
    float* __restrict__ out, int nW)
{
    __shared__ float zs[BATCH*ZDIM];
    for (int i = threadIdx.x; i < BATCH*ZDIM; i += 256) zs[i] = z[i];
    __syncthreads();

    int i = blockIdx.x * 256 + threadIdx.x;
    if (i >= nW) return;

    float4 hwv[16];
    const float4* hwp = (const float4*)(hw + (size_t)i * ZDIM);
#pragma unroll
    for (int j = 0; j < 16; j++) hwv[j] = hwp[j];

    const float c = base[i] + hb[i];
#pragma unroll
    for (int b = 0; b < BATCH; b++) {
        const float* zb = zs + b * ZDIM;
        float acc = 0.f;
#pragma unroll
        for (int j = 0; j < 16; j++) {
            acc += hwv[j].x * zb[4*j+0];
            acc += hwv[j].y * zb[4*j+1];
            acc += hwv[j].z * zb[4*j+2];
            acc += hwv[j].w * zb[4*j+3];
        }
        out[(size_t)b * nW + i] = c + acc;
    }
}

// ---------------------------------------------------------------------------
// Tiled direct conv, per-batch weights.
// Block tile: 64 output channels x 8x8 output pixels. 256 threads.
// Thread tile: 4 oc x 4 px (register-blocked: 8 LDS per 16 FFMA).
// Grid: (16 spatial tiles, OC/64, B)
// ---------------------------------------------------------------------------
template<int KS, int STRIDE, int IC>
__global__ __launch_bounds__(256) void conv_kernel(
    const float* __restrict__ x, const float* __restrict__ w,
    float* __restrict__ out, int Hin, int Win)
{
    constexpr int PAD  = KS / 2;
    constexpr int ICC  = 8;
    constexpr int XT   = 7 * STRIDE + KS;        // input span for 8 outputs
    constexpr int XTW  = XT + 1;                 // pad to break conflicts
    constexpr int KK   = KS * KS;
    constexpr int WSTR = ICC * KK + 1;           // per-oc smem stride (odd)

    __shared__ float xs[ICC][XT][XTW];
    __shared__ float ws[64][WSTR];

    const int b   = blockIdx.z;
    const int oc0 = blockIdx.y * 64;
    const int tw0 = (blockIdx.x % (WO/8)) * 8;
    const int th0 = (blockIdx.x / (WO/8)) * 8;

    const float* xb = x + (size_t)b * IC * Hin * Win;
    const float* wb = w + ((size_t)b * OCN + oc0) * IC * KK;

    const int tx  = threadIdx.x;
    const int pr  = (tx & 15) >> 1;      // pixel row within 8x8
    const int pc0 = (tx & 1) * 4;        // pixel col base
    const int oci = (tx >> 4) * 4;       // local oc base

    float acc[4][4] = {};

    for (int ic0 = 0; ic0 < IC; ic0 += ICC) {
        // load input patch (zero-padded)
        for (int i = tx; i < ICC * XT * XT; i += 256) {
            int ic = i / (XT * XT);
            int r  = (i / XT) % XT;
            int c  = i % XT;
            int ih = th0 * STRIDE - PAD + r;
            int iw = tw0 * STRIDE - PAD + c;
            float v = 0.f;
            if (ih >= 0 && ih < Hin && iw >= 0 && iw < Win)
                v = xb[(size_t)(ic0 + ic) * Hin * Win + ih * Win + iw];
            xs[ic][r][c] = v;
        }
        // load weights (contiguous per oc slice)
        for (int i = tx; i < 64 * ICC * KK; i += 256) {
            int oc = i / (ICC * KK);
            int j  = i % (ICC * KK);
            ws[oc][j] = wb[(size_t)oc * IC * KK + ic0 * KK + j];
        }
        __syncthreads();

#pragma unroll
        for (int ic = 0; ic < ICC; ic++) {
#pragma unroll
            for (int kh = 0; kh < KS; kh++) {
#pragma unroll
                for (int kw = 0; kw < KS; kw++) {
                    float wv[4], xv[4];
#pragma unroll
                    for (int i = 0; i < 4; i++)
                        wv[i] = ws[oci + i][ic * KK + kh * KS + kw];
#pragma unroll
                    for (int j = 0; j < 4; j++)
                        xv[j] = xs[ic][pr * STRIDE + kh][(pc0 + j) * STRIDE + kw];
#pragma unroll
                    for (int i = 0; i < 4; i++)
#pragma unroll
                        for (int j = 0; j < 4; j++)
                            acc[i][j] += wv[i] * xv[j];
                }
            }
        }
        __syncthreads();
    }

#pragma unroll
    for (int i = 0; i < 4; i++) {
        size_t o = ((size_t)b * OCN + oc0 + oci + i) * NPIX + (th0 + pr) * WO + tw0 + pc0;
#pragma unroll
        for (int j = 0; j < 4; j++) out[o + j] = acc[i][j];
    }
}

// ---------------------------------------------------------------------------
// GroupNorm statistics: one block per (b, group); group data is contiguous
// (32 channels * 1024 px = 32768 floats). stats = {mean, rsqrt(var+eps)}.
// ---------------------------------------------------------------------------
__global__ __launch_bounds__(256) void gn_stats_kernel(
    const float* __restrict__ x, float* __restrict__ stats)
{
    const int bg = blockIdx.x;
    const float* p = x + (size_t)bg * (CPG * NPIX);
    float s = 0.f, ss = 0.f;
    for (int i = threadIdx.x; i < CPG * NPIX; i += 256) {
        float v = p[i];
        s += v; ss += v * v;
    }
    __shared__ float sh0[256], sh1[256];
    sh0[threadIdx.x] = s; sh1[threadIdx.x] = ss;
    __syncthreads();
    for (int o = 128; o > 0; o >>= 1) {
        if (threadIdx.x < o) {
            sh0[threadIdx.x] += sh0[threadIdx.x + o];
            sh1[threadIdx.x] += sh1[threadIdx.x + o];
        }
        __syncthreads();
    }
    if (threadIdx.x == 0) {
        const float n   = (float)(CPG * NPIX);
        float mu  = sh0[0] / n;
        float var = sh1[0] / n - mu * mu;
        stats[bg * 2 + 0] = mu;
        stats[bg * 2 + 1] = rsqrtf(var + EPSV);
    }
}

// GN1 apply + ReLU, in place
__global__ __launch_bounds__(256) void gn1_apply_kernel(
    float* __restrict__ x, const float* __restrict__ stats,
    const float* __restrict__ gamma, const float* __restrict__ beta)
{
    int idx = blockIdx.x * 256 + threadIdx.x;     // grid sized exactly
    int c   = (idx >> 10) & 255;                  // idx / 1024 mod 256
    int bg  = idx >> 15;                          // idx / 32768
    float mu = stats[bg * 2], ri = stats[bg * 2 + 1];
    float v  = (x[idx] - mu) * ri * gamma[c] + beta[c];
    x[idx] = fmaxf(v, 0.f);
}

// Final: out = relu(gn2(conv2) + shortcut)
__global__ __launch_bounds__(256) void final_kernel(
    const float* __restrict__ x, const float* __restrict__ sc,
    const float* __restrict__ stats,
    const float* __restrict__ gamma, const float* __restrict__ beta,
    float* __restrict__ out)
{
    int idx = blockIdx.x * 256 + threadIdx.x;
    int c   = (idx >> 10) & 255;
    int bg  = idx >> 15;
    float mu = stats[bg * 2], ri = stats[bg * 2 + 1];
    float v  = (x[idx] - mu) * ri * gamma[c] + beta[c] + sc[idx];
    out[idx] = fmaxf(v, 0.f);
}

// ---------------------------------------------------------------------------
extern "C" void kernel_launch(void* const* d_in, const int* in_sizes, int n_in,
                              void* d_out, int out_size)
{
    const float* x        = (const float*)d_in[0];
    const float* z        = (const float*)d_in[1];
    const float* base_w1  = (const float*)d_in[2];
    const float* head_w1  = (const float*)d_in[3];
    const float* head_b1  = (const float*)d_in[4];
    const float* gn_w1    = (const float*)d_in[5];
    const float* gn_b1    = (const float*)d_in[6];
    const float* base_w2  = (const float*)d_in[7];
    const float* head_w2  = (const float*)d_in[8];
    const float* head_b2  = (const float*)d_in[9];
    const float* gn_w2    = (const float*)d_in[10];
    const float* gn_b2    = (const float*)d_in[11];
    const float* base_wsc = (const float*)d_in[12];
    const float* head_wsc = (const float*)d_in[13];
    const float* head_bsc = (const float*)d_in[14];
    float* out = (float*)d_out;

    float *w1p, *w2p, *wscp, *a1p, *c2p, *scp, *st1p, *st2p;
    cudaGetSymbolAddress((void**)&w1p,  g_w1);
    cudaGetSymbolAddress((void**)&w2p,  g_w2);
    cudaGetSymbolAddress((void**)&wscp, g_wsc);
    cudaGetSymbolAddress((void**)&a1p,  g_act1);
    cudaGetSymbolAddress((void**)&c2p,  g_conv2);
    cudaGetSymbolAddress((void**)&scp,  g_sc);
    cudaGetSymbolAddress((void**)&st1p, g_stats1);
    cudaGetSymbolAddress((void**)&st2p, g_stats2);

    // 1. modulated weights
    modw_kernel<<<NW1  / 256, 256>>>(base_w1,  head_w1,  head_b1,  z, w1p,  NW1);
    modw_kernel<<<NW2  / 256, 256>>>(base_w2,  head_w2,  head_b2,  z, w2p,  NW2);
    modw_kernel<<<NWSC / 256, 256>>>(base_wsc, head_wsc, head_bsc, z, wscp, NWSC);

    // 2. conv1 (3x3, stride 2) and shortcut (1x1, stride 2)
    dim3 cgrid(16, OCN / 64, BATCH);
    conv_kernel<3, 2, IC1><<<cgrid, 256>>>(x, w1p,  a1p, HIN, WIN);
    conv_kernel<1, 2, IC1><<<cgrid, 256>>>(x, wscp, scp, HIN, WIN);

    // 3. GN1 + ReLU (in place on act1)
    gn_stats_kernel<<<BATCH * NGRP, 256>>>(a1p, st1p);
    gn1_apply_kernel<<<(BATCH * OCN * NPIX) / 256, 256>>>(a1p, st1p, gn_w1, gn_b1);

    // 4. conv2 (3x3, stride 1)
    conv_kernel<3, 1, OCN><<<cgrid, 256>>>(a1p, w2p, c2p, HO, WO);

    // 5. GN2 + residual + ReLU -> out
    gn_stats_kernel<<<BATCH * NGRP, 256>>>(c2p, st2p);
    final_kernel<<<(BATCH * OCN * NPIX) / 256, 256>>>(c2p, scp, st2p, gn_w2, gn_b2, out);
}